// round 15
// baseline (speedup 1.0000x reference)
#include <cuda_runtime.h>

#define TT   8
#define NS   512
#define NTOT 32768   // NS*NP

// Scratch: GAT output -> graph LSTM input ([T, N, 32])
__device__ float g_graph_in[(size_t)TT * NTOT * 32];
// Scratch: precomputed input-gate contributions for graph LSTM
// layout: [(t*16384 + ped_pair)][gate*32 + k] as (even,odd)-ped f32 pairs
__device__ unsigned long long g_xg[(size_t)TT * 16384 * 128];

typedef unsigned long long u64;
typedef unsigned int u32;

__device__ __forceinline__ u64 ffma2(u64 a, u64 b, u64 c) {
    u64 d;
    asm("fma.rn.f32x2 %0, %1, %2, %3;" : "=l"(d) : "l"(a), "l"(b), "l"(c));
    return d;
}
__device__ __forceinline__ u64 pk2(float lo, float hi) {
    u64 r;
    asm("mov.b64 %0, {%1, %2};" : "=l"(r) : "f"(lo), "f"(hi));
    return r;
}
__device__ __forceinline__ float lo2(u64 v) { return __uint_as_float((unsigned)v); }
__device__ __forceinline__ float hi2(u64 v) { return __uint_as_float((unsigned)(v >> 32)); }

__device__ __forceinline__ float sigmf_(float x) {
    return __fdividef(1.f, 1.f + __expf(-x));
}
__device__ __forceinline__ float tanhf_(float x) {
    float e = __expf(-2.f * fabsf(x));
    float r = __fdividef(1.f - e, 1.f + e);
    return copysignf(r, x);
}

// ---------------------------------------------------------------------------
// xg_kernel: XG[t][pair][gate,k] = Wih @ x + (bih+bhh), fully parallel GEMM.
// Block = 256 threads, 32 ped-pairs; warp w handles pairs w*4..w*4+3.
// ---------------------------------------------------------------------------
__global__ void __launch_bounds__(256, 2) xg_kernel(
    const float* __restrict__ gin,   // [T, N, 32]
    const float* __restrict__ Wih,   // [128, 32]
    const float* __restrict__ bih, const float* __restrict__ bhh,
    u64* __restrict__ xgp)
{
    __shared__ __align__(16) u64 WD[128 * 34];
    __shared__ __align__(16) u64 XP[32 * 34];
    __shared__ float SB[128];

    const int tid = threadIdx.x;
    const int b = blockIdx.x;
    const int t = b >> 9;
    const int pb = (b & 511) * 32;           // pair base

    for (int i = tid; i < 128 * 32; i += 256) {
        int r = i >> 5, f = i & 31;
        float w = Wih[r * 32 + f];
        WD[r * 34 + f] = pk2(w, w);
    }
    if (tid < 128) SB[tid] = bih[tid] + bhh[tid];
    {
        const int p  = tid >> 2;             // local ped 0..63
        const int fo = (tid & 3) << 3;
        const float4* xp = reinterpret_cast<const float4*>(
            gin + ((size_t)t * NTOT + 2 * pb + p) * 32 + fo);
        float4 A = xp[0], Bq = xp[1];
        float av[8] = {A.x, A.y, A.z, A.w, Bq.x, Bq.y, Bq.z, Bq.w};
        u32* XH = reinterpret_cast<u32*>(XP);
        #pragma unroll
        for (int e = 0; e < 8; e++)
            XH[2 * ((fo + e) * 34 + (p >> 1)) + (p & 1)] = __float_as_uint(av[e]);
    }
    __syncthreads();

    const int k   = tid & 31;
    const int pg4 = (tid >> 5) * 4;
    const int kb0 = (0 * 32 + k) * 34;
    const int kb1 = (1 * 32 + k) * 34;
    const int kb2 = (2 * 32 + k) * 34;
    const int kb3 = (3 * 32 + k) * 34;

    u64 aI[4] = {0,0,0,0}, aF[4] = {0,0,0,0}, aG[4] = {0,0,0,0}, aO[4] = {0,0,0,0};
    #pragma unroll
    for (int fo = 0; fo < 8; fo++) {
        const int f4 = fo * 4;
        u64 wv[4][4];
        {
            ulonglong2 q;
            q = *(const ulonglong2*)&WD[kb0 + f4];     wv[0][0] = q.x; wv[0][1] = q.y;
            q = *(const ulonglong2*)&WD[kb0 + f4 + 2]; wv[0][2] = q.x; wv[0][3] = q.y;
            q = *(const ulonglong2*)&WD[kb1 + f4];     wv[1][0] = q.x; wv[1][1] = q.y;
            q = *(const ulonglong2*)&WD[kb1 + f4 + 2]; wv[1][2] = q.x; wv[1][3] = q.y;
            q = *(const ulonglong2*)&WD[kb2 + f4];     wv[2][0] = q.x; wv[2][1] = q.y;
            q = *(const ulonglong2*)&WD[kb2 + f4 + 2]; wv[2][2] = q.x; wv[2][3] = q.y;
            q = *(const ulonglong2*)&WD[kb3 + f4];     wv[3][0] = q.x; wv[3][1] = q.y;
            q = *(const ulonglong2*)&WD[kb3 + f4 + 2]; wv[3][2] = q.x; wv[3][3] = q.y;
        }
        u64 xv[4][4];
        #pragma unroll
        for (int fp = 0; fp < 4; fp++) {
            ulonglong2 q0 = *(const ulonglong2*)&XP[(f4 + fp) * 34 + pg4];
            ulonglong2 q1 = *(const ulonglong2*)&XP[(f4 + fp) * 34 + pg4 + 2];
            xv[fp][0] = q0.x; xv[fp][1] = q0.y; xv[fp][2] = q1.x; xv[fp][3] = q1.y;
        }
        #pragma unroll
        for (int fp = 0; fp < 4; fp++) {
            #pragma unroll
            for (int pp = 0; pp < 4; pp++) {
                aI[pp] = ffma2(wv[0][fp], xv[fp][pp], aI[pp]);
                aF[pp] = ffma2(wv[1][fp], xv[fp][pp], aF[pp]);
                aG[pp] = ffma2(wv[2][fp], xv[fp][pp], aG[pp]);
                aO[pp] = ffma2(wv[3][fp], xv[fp][pp], aO[pp]);
            }
        }
    }

    const float bI = SB[k], bF = SB[32 + k], bG = SB[64 + k], bO = SB[96 + k];
    #pragma unroll
    for (int pp = 0; pp < 4; pp++) {
        u64* row = xgp + (((size_t)t * 16384 + pb + pg4 + pp) << 7);
        row[k]      = pk2(lo2(aI[pp]) + bI, hi2(aI[pp]) + bI);
        row[32 + k] = pk2(lo2(aF[pp]) + bF, hi2(aF[pp]) + bF);
        row[64 + k] = pk2(lo2(aG[pp]) + bG, hi2(aG[pp]) + bG);
        row[96 + k] = pk2(lo2(aO[pp]) + bO, hi2(aO[pp]) + bO);
    }
}

// ---------------------------------------------------------------------------
// LSTM as per-step tiled GEMM. XGM=true: input-gate contributions come from
// precomputed XG (loaded mid-GEMM, latency hidden by remaining FFMA2).
// ---------------------------------------------------------------------------
template<int D, bool ENC, bool XGM>
__global__ void __launch_bounds__(256, 2) lstm_kernel(
    const float* __restrict__ xseq,    // [T, N, D] (unused when XGM)
    const float* __restrict__ h0, const float* __restrict__ c0,   // [N,32]
    const float* __restrict__ Wih,     // [128, D] (unused when XGM)
    const float* __restrict__ Whh,     // [128, 32]
    const float* __restrict__ bih, const float* __restrict__ bhh, // [128]
    float* __restrict__ hsout,         // [T, N, 32]
    const u64* __restrict__ xgp,       // XG pairs (XGM only)
    const float* __restrict__ traj_last, // [N,32] (ENC only)
    const float* __restrict__ znoise,    // [S,8]  (ENC only)
    float* __restrict__ enc)             // [N,72] (ENC only)
{
    constexpr int SWH    = 34;
    constexpr int SWX    = (D == 3) ? 5 : 34;
    constexpr int WDH_SZ = 128 * SWH;
    constexpr int WDX_SZ = XGM ? 0 : 128 * SWX;
    constexpr int HB_SZ  = 2 * 32 * 34;
    constexpr int HSTRIDE = 32 * 34;

    extern __shared__ __align__(16) u64 smU[];
    u64* WDH = smU;
    u64* WDX = WDH + WDH_SZ;
    u64* HB  = WDX + WDX_SZ;
    u64* XB  = HB + HB_SZ;

    const int tid  = threadIdx.x;
    const int k    = tid & 31;
    const int pg   = tid >> 5;
    const int pg4  = pg * 4;
    const int base = blockIdx.x * 64;

    for (int i = tid; i < 128 * 32; i += 256) {
        int r = i >> 5, f = i & 31;
        float w = Whh[r * 32 + f];
        WDH[r * SWH + f] = pk2(w, w);
    }
    if constexpr (!XGM) {
        if constexpr (D == 3) {
            for (int i = tid; i < 128 * 3; i += 256) {
                int r = i / 3, f = i - r * 3;
                float w = Wih[r * 3 + f];
                WDX[r * SWX + f] = pk2(w, w);
            }
        } else {
            for (int i = tid; i < 128 * 32; i += 256) {
                int r = i >> 5, f = i & 31;
                float w = Wih[r * 32 + f];
                WDX[r * SWX + f] = pk2(w, w);
            }
        }
    }

    float bI = 0.f, bF = 0.f, bG = 0.f, bO = 0.f;
    if constexpr (!XGM) {
        bI = bih[k]      + bhh[k];
        bF = bih[32 + k] + bhh[32 + k];
        bG = bih[64 + k] + bhh[64 + k];
        bO = bih[96 + k] + bhh[96 + k];
    }

    float c[8];
    {
        float hv0[8];
        #pragma unroll
        for (int j = 0; j < 8; j++) {
            c[j]   = c0[(size_t)(base + pg * 8 + j) * 32 + k];
            hv0[j] = h0[(size_t)(base + pg * 8 + j) * 32 + k];
        }
        u64* HN = HB + (size_t)k * 34 + pg4;
        #pragma unroll
        for (int jj = 0; jj < 4; jj++) HN[jj] = pk2(hv0[2*jj], hv0[2*jj+1]);
    }

    if constexpr (!XGM) {
        if constexpr (D == 3) {
            u32* XH = reinterpret_cast<u32*>(XB);
            for (int i = tid; i < 8 * 64 * 3; i += 256) {
                int tt  = i / 192;
                int rem = i - tt * 192;
                int p   = rem / 3;
                int xf  = rem - p * 3;
                float xv = xseq[((size_t)tt * NTOT + base + p) * 3 + xf];
                XH[2 * ((tt * 3 + xf) * 34 + (p >> 1)) + (p & 1)] = __float_as_uint(xv);
            }
        }
    }
    __syncthreads();

    const int kb0 = (0 * 32 + k) * SWH;
    const int kb1 = (1 * 32 + k) * SWH;
    const int kb2 = (2 * 32 + k) * SWH;
    const int kb3 = (3 * 32 + k) * SWH;

    #pragma unroll 1
    for (int t = 0; t < TT; t++) {
        u64 aI[4] = {0,0,0,0}, aF[4] = {0,0,0,0}, aG[4] = {0,0,0,0}, aO[4] = {0,0,0,0};
        u64 xI[4], xF[4], xGt[4], xO[4];

        const u64* HT = HB + (t & 1) * HSTRIDE;
        // --- h GEMM first half (fo 0..3) ---
        #pragma unroll
        for (int fo = 0; fo < 4; fo++) {
            const int f4 = fo * 4;
            u64 wv[4][4];
            {
                ulonglong2 q;
                q = *(const ulonglong2*)&WDH[kb0 + f4];     wv[0][0] = q.x; wv[0][1] = q.y;
                q = *(const ulonglong2*)&WDH[kb0 + f4 + 2]; wv[0][2] = q.x; wv[0][3] = q.y;
                q = *(const ulonglong2*)&WDH[kb1 + f4];     wv[1][0] = q.x; wv[1][1] = q.y;
                q = *(const ulonglong2*)&WDH[kb1 + f4 + 2]; wv[1][2] = q.x; wv[1][3] = q.y;
                q = *(const ulonglong2*)&WDH[kb2 + f4];     wv[2][0] = q.x; wv[2][1] = q.y;
                q = *(const ulonglong2*)&WDH[kb2 + f4 + 2]; wv[2][2] = q.x; wv[2][3] = q.y;
                q = *(const ulonglong2*)&WDH[kb3 + f4];     wv[3][0] = q.x; wv[3][1] = q.y;
                q = *(const ulonglong2*)&WDH[kb3 + f4 + 2]; wv[3][2] = q.x; wv[3][3] = q.y;
            }
            u64 hv[4][4];
            #pragma unroll
            for (int fp = 0; fp < 4; fp++) {
                ulonglong2 q0 = *(const ulonglong2*)&HT[(f4 + fp) * 34 + pg4];
                ulonglong2 q1 = *(const ulonglong2*)&HT[(f4 + fp) * 34 + pg4 + 2];
                hv[fp][0] = q0.x; hv[fp][1] = q0.y; hv[fp][2] = q1.x; hv[fp][3] = q1.y;
            }
            #pragma unroll
            for (int fp = 0; fp < 4; fp++) {
                #pragma unroll
                for (int pp = 0; pp < 4; pp++) {
                    aI[pp] = ffma2(wv[0][fp], hv[fp][pp], aI[pp]);
                    aF[pp] = ffma2(wv[1][fp], hv[fp][pp], aF[pp]);
                    aG[pp] = ffma2(wv[2][fp], hv[fp][pp], aG[pp]);
                    aO[pp] = ffma2(wv[3][fp], hv[fp][pp], aO[pp]);
                }
            }
        }

        // --- XG loads issued mid-GEMM: second GEMM half hides DRAM latency ---
        if constexpr (XGM) {
            const u64* xr = xgp + ((size_t)t * 16384 + (base >> 1) + pg4) * 128;
            #pragma unroll
            for (int pp = 0; pp < 4; pp++) {
                const u64* r = xr + (size_t)pp * 128;
                xI[pp] = r[k]; xF[pp] = r[32 + k]; xGt[pp] = r[64 + k]; xO[pp] = r[96 + k];
            }
        }

        // --- h GEMM second half (fo 4..7) ---
        #pragma unroll
        for (int fo = 4; fo < 8; fo++) {
            const int f4 = fo * 4;
            u64 wv[4][4];
            {
                ulonglong2 q;
                q = *(const ulonglong2*)&WDH[kb0 + f4];     wv[0][0] = q.x; wv[0][1] = q.y;
                q = *(const ulonglong2*)&WDH[kb0 + f4 + 2]; wv[0][2] = q.x; wv[0][3] = q.y;
                q = *(const ulonglong2*)&WDH[kb1 + f4];     wv[1][0] = q.x; wv[1][1] = q.y;
                q = *(const ulonglong2*)&WDH[kb1 + f4 + 2]; wv[1][2] = q.x; wv[1][3] = q.y;
                q = *(const ulonglong2*)&WDH[kb2 + f4];     wv[2][0] = q.x; wv[2][1] = q.y;
                q = *(const ulonglong2*)&WDH[kb2 + f4 + 2]; wv[2][2] = q.x; wv[2][3] = q.y;
                q = *(const ulonglong2*)&WDH[kb3 + f4];     wv[3][0] = q.x; wv[3][1] = q.y;
                q = *(const ulonglong2*)&WDH[kb3 + f4 + 2]; wv[3][2] = q.x; wv[3][3] = q.y;
            }
            u64 hv[4][4];
            #pragma unroll
            for (int fp = 0; fp < 4; fp++) {
                ulonglong2 q0 = *(const ulonglong2*)&HT[(f4 + fp) * 34 + pg4];
                ulonglong2 q1 = *(const ulonglong2*)&HT[(f4 + fp) * 34 + pg4 + 2];
                hv[fp][0] = q0.x; hv[fp][1] = q0.y; hv[fp][2] = q1.x; hv[fp][3] = q1.y;
            }
            #pragma unroll
            for (int fp = 0; fp < 4; fp++) {
                #pragma unroll
                for (int pp = 0; pp < 4; pp++) {
                    aI[pp] = ffma2(wv[0][fp], hv[fp][pp], aI[pp]);
                    aF[pp] = ffma2(wv[1][fp], hv[fp][pp], aF[pp]);
                    aG[pp] = ffma2(wv[2][fp], hv[fp][pp], aG[pp]);
                    aO[pp] = ffma2(wv[3][fp], hv[fp][pp], aO[pp]);
                }
            }
        }

        // --- x contribution for non-XG mode (D==3 only in practice) ---
        if constexpr (!XGM && D == 3) {
            const u64* XT = XB + (size_t)t * (3 * 34);
            const int xb0 = (0 * 32 + k) * SWX;
            const int xb1 = (1 * 32 + k) * SWX;
            const int xb2 = (2 * 32 + k) * SWX;
            const int xb3 = (3 * 32 + k) * SWX;
            #pragma unroll
            for (int xf = 0; xf < 3; xf++) {
                u64 wI = WDX[xb0 + xf], wF = WDX[xb1 + xf];
                u64 wG = WDX[xb2 + xf], wO = WDX[xb3 + xf];
                ulonglong2 q0 = *(const ulonglong2*)&XT[xf * 34 + pg4];
                ulonglong2 q1 = *(const ulonglong2*)&XT[xf * 34 + pg4 + 2];
                u64 xv[4] = {q0.x, q0.y, q1.x, q1.y};
                #pragma unroll
                for (int pp = 0; pp < 4; pp++) {
                    aI[pp] = ffma2(wI, xv[pp], aI[pp]);
                    aF[pp] = ffma2(wF, xv[pp], aF[pp]);
                    aG[pp] = ffma2(wG, xv[pp], aG[pp]);
                    aO[pp] = ffma2(wO, xv[pp], aO[pp]);
                }
            }
        }

        // --- activations: 8 peds, unit k ---
        float hvec[8];
        #pragma unroll
        for (int pp = 0; pp < 4; pp++) {
            {
                const int p = 2 * pp;
                float gi = lo2(aI[pp]) + (XGM ? lo2(xI[pp])  : bI);
                float gf = lo2(aF[pp]) + (XGM ? lo2(xF[pp])  : bF);
                float gg = lo2(aG[pp]) + (XGM ? lo2(xGt[pp]) : bG);
                float go = lo2(aO[pp]) + (XGM ? lo2(xO[pp])  : bO);
                float cn = sigmf_(gf) * c[p] + sigmf_(gi) * tanhf_(gg);
                c[p] = cn;
                hvec[p] = sigmf_(go) * tanhf_(cn);
            }
            {
                const int p = 2 * pp + 1;
                float gi = hi2(aI[pp]) + (XGM ? hi2(xI[pp])  : bI);
                float gf = hi2(aF[pp]) + (XGM ? hi2(xF[pp])  : bF);
                float gg = hi2(aG[pp]) + (XGM ? hi2(xGt[pp]) : bG);
                float go = hi2(aO[pp]) + (XGM ? hi2(xO[pp])  : bO);
                float cn = sigmf_(gf) * c[p] + sigmf_(gi) * tanhf_(gg);
                c[p] = cn;
                hvec[p] = sigmf_(go) * tanhf_(cn);
            }
        }

        const int pedbase = base + pg * 8;
        #pragma unroll
        for (int j = 0; j < 8; j++)
            hsout[((size_t)t * NTOT + pedbase + j) * 32 + k] = hvec[j];

        if (t < TT - 1) {
            u64* HN = HB + ((t + 1) & 1) * HSTRIDE + (size_t)k * 34 + pg4;
            #pragma unroll
            for (int jj = 0; jj < 4; jj++) HN[jj] = pk2(hvec[2*jj], hvec[2*jj+1]);
            __syncthreads();
        } else if (ENC) {
            #pragma unroll
            for (int j = 0; j < 8; j++) {
                float* ep = enc + (size_t)(pedbase + j) * 72;
                ep[32 + k] = hvec[j];
                ep[k] = traj_last[(size_t)(pedbase + j) * 32 + k];
            }
            if (k < 8) {
                const float z = znoise[(size_t)blockIdx.x * 8 + k];
                #pragma unroll
                for (int j = 0; j < 8; j++)
                    enc[(size_t)(pedbase + j) * 72 + 64 + k] = z;
            }
        }
    }
}

// ---------------------------------------------------------------------------
// GAT encoder: 2 tiles per block (weights staged once). 256 threads.
// ---------------------------------------------------------------------------
#define GAT_SMEM_FLOATS 18160
#define GAT_SMEM_BYTES  (GAT_SMEM_FLOATS * 4)

__global__ void __launch_bounds__(256, 3) gat_kernel(
    const float* __restrict__ trajhs,   // [T, N, 32]
    const float* __restrict__ w0,       // [4,32,16]
    const float* __restrict__ asrc0, const float* __restrict__ adst0,  // [4,16]
    const float* __restrict__ bias0,    // [16]
    const float* __restrict__ w1,       // [1,64,32]
    const float* __restrict__ asrc1, const float* __restrict__ adst1,  // [32]
    const float* __restrict__ bias1,    // [32]
    float* __restrict__ gout)           // [T, N, 32]
{
    extern __shared__ __align__(16) float sm[];
    float* XN  = sm;           // 64 x 33   (dead after hp0)
    float* W0S = sm + 2112;    // 32 x 64   (persistent across tiles)
    float* HP0 = sm + 4160;    // 64 x 68   (dead after attn0)
    float* EM  = sm + 4160;    // 64 x 68   overlays HP0
    float* S0  = sm + 8512;    // 4 x 64
    float* D0  = sm + 8768;    // 4 x 64
    float* X1  = sm + 9024;    // 64 x 68
    float* W1S = sm + 13376;   // 64 x 32   (persistent)
    float* HP1 = sm + 15424;   // 64 x 36
    float* S1  = sm + 17728;   // 64
    float* D1  = sm + 17792;   // 64
    float* ES  = sm + 17856;   // 64
    float* A0S = sm + 17920;   // 64
    float* A0D = sm + 17984;   // 64
    float* A1S = sm + 18048;   // 32
    float* A1D = sm + 18080;   // 32
    float* B0  = sm + 18112;   // 16
    float* B1  = sm + 18128;   // 32

    const int tid = threadIdx.x;

    // ---- stage persistent weights once ----
    for (int i = tid; i < 2048; i += 256) {
        int f = i >> 6, cc = i & 63;
        W0S[i] = w0[((cc >> 4) << 9) + (f << 4) + (cc & 15)];
    }
    for (int i = tid; i < 2048; i += 256) W1S[i] = w1[i];
    if (tid < 64)       { A0S[tid] = asrc0[tid]; A0D[tid] = adst0[tid]; }
    else if (tid < 96)  { A1S[tid - 64] = asrc1[tid - 64]; A1D[tid - 64] = adst1[tid - 64]; }
    else if (tid < 112) { B0[tid - 96] = bias0[tid - 96]; }
    else if (tid < 144) { B1[tid - 112] = bias1[tid - 112]; }

    #pragma unroll 1
    for (int tl = 0; tl < 2; tl++) {
        const int tile = blockIdx.x * 2 + tl;
        const int s = tile >> 3, t = tile & 7;

        const float* src = trajhs + ((size_t)t * NTOT + s * 64) * 32;
        for (int i = tid; i < 2048; i += 256) XN[(i >> 5) * 33 + (i & 31)] = src[i];
        __syncthreads();

        // --- instance norm 0 ---
        {
            const int f = tid >> 3, g = tid & 7;
            float mval = 0.f;
            #pragma unroll
            for (int i = 0; i < 8; i++) mval += XN[(g + 8 * i) * 33 + f];
            mval += __shfl_xor_sync(0xFFFFFFFFu, mval, 1);
            mval += __shfl_xor_sync(0xFFFFFFFFu, mval, 2);
            mval += __shfl_xor_sync(0xFFFFFFFFu, mval, 4);
            const float m = mval * 0.015625f;
            float v = 0.f;
            #pragma unroll
            for (int i = 0; i < 8; i++) { float d = XN[(g + 8 * i) * 33 + f] - m; v = fmaf(d, d, v); }
            v += __shfl_xor_sync(0xFFFFFFFFu, v, 1);
            v += __shfl_xor_sync(0xFFFFFFFFu, v, 2);
            v += __shfl_xor_sync(0xFFFFFFFFu, v, 4);
            const float inv = rsqrtf(fmaf(v, 0.015625f, 1e-5f));
            #pragma unroll
            for (int i = 0; i < 8; i++) {
                const int idx = (g + 8 * i) * 33 + f;
                XN[idx] = (XN[idx] - m) * inv;
            }
        }
        __syncthreads();

        // --- hp0 = xn @ w0, fused s0/d0 ---
        {
            const int p  = tid >> 2;
            const int h  = tid & 3;
            const int cb = h << 4;
            u64 acc[8] = {0, 0, 0, 0, 0, 0, 0, 0};
            #pragma unroll
            for (int f = 0; f < 32; f++) {
                float xv = XN[p * 33 + f];
                u64 xx = pk2(xv, xv);
                const ulonglong2* w = reinterpret_cast<const ulonglong2*>(W0S + f * 64 + cb);
                #pragma unroll
                for (int j = 0; j < 4; j++) {
                    ulonglong2 ww = w[j];
                    acc[2*j]   = ffma2(ww.x, xx, acc[2*j]);
                    acc[2*j+1] = ffma2(ww.y, xx, acc[2*j+1]);
                }
            }
            float sv = 0.f, dv = 0.f;
            #pragma unroll
            for (int j = 0; j < 8; j++) {
                float v0 = lo2(acc[j]), v1 = hi2(acc[j]);
                sv = fmaf(v0, A0S[cb + 2*j], sv); sv = fmaf(v1, A0S[cb + 2*j + 1], sv);
                dv = fmaf(v0, A0D[cb + 2*j], dv); dv = fmaf(v1, A0D[cb + 2*j + 1], dv);
            }
            S0[h * 64 + p] = sv;
            D0[h * 64 + p] = dv;
            u64* dst = reinterpret_cast<u64*>(HP0 + p * 68 + cb);
            #pragma unroll
            for (int j = 0; j < 8; j++) dst[j] = acc[j];
        }
        __syncthreads();

        // --- attention0 (no max-pass, batched exp) -> X1 ---
        {
            const int h = tid >> 6, p = tid & 63;
            const float sp = S0[h * 64 + p];
            const float* dd = D0 + h * 64;
            u64 acc[8] = {0, 0, 0, 0, 0, 0, 0, 0};
            float den = 0.f;
            #pragma unroll 1
            for (int qb = 0; qb < 8; qb++) {
                float4 da = *(const float4*)(dd + qb * 8);
                float4 db = *(const float4*)(dd + qb * 8 + 4);
                float e[8] = {da.x, da.y, da.z, da.w, db.x, db.y, db.z, db.w};
                float w[8];
                #pragma unroll
                for (int i = 0; i < 8; i++) {
                    float ev = sp + e[i];
                    ev = ev > 0.f ? ev : 0.2f * ev;
                    w[i] = __expf(ev);
                }
                #pragma unroll
                for (int i = 0; i < 8; i++) den += w[i];
                #pragma unroll
                for (int i = 0; i < 8; i++) {
                    u64 ww = pk2(w[i], w[i]);
                    const ulonglong2* hq = reinterpret_cast<const ulonglong2*>(
                        HP0 + (qb * 8 + i) * 68 + h * 16);
                    ulonglong2 h0q = hq[0], h1q = hq[1], h2q = hq[2], h3q = hq[3];
                    acc[0] = ffma2(h0q.x, ww, acc[0]); acc[1] = ffma2(h0q.y, ww, acc[1]);
                    acc[2] = ffma2(h1q.x, ww, acc[2]); acc[3] = ffma2(h1q.y, ww, acc[3]);
                    acc[4] = ffma2(h2q.x, ww, acc[4]); acc[5] = ffma2(h2q.y, ww, acc[5]);
                    acc[6] = ffma2(h3q.x, ww, acc[6]); acc[7] = ffma2(h3q.y, ww, acc[7]);
                }
            }
            float inv = __fdividef(1.f, den);
            float* xo = X1 + p * 68 + h * 16;
            #pragma unroll
            for (int j = 0; j < 8; j++) {
                float v0 = fmaf(lo2(acc[j]), inv, B0[2 * j]);
                float v1 = fmaf(hi2(acc[j]), inv, B0[2 * j + 1]);
                v0 = v0 > 0.f ? v0 : expm1f(v0);
                v1 = v1 > 0.f ? v1 : expm1f(v1);
                xo[2 * j] = v0;
                xo[2 * j + 1] = v1;
            }
        }
        __syncthreads();

        // --- instance norm 1 ---
        {
            const int f = tid >> 2, g = tid & 3;
            float mval = 0.f;
            #pragma unroll
            for (int i = 0; i < 16; i++) mval += X1[(g + 4 * i) * 68 + f];
            mval += __shfl_xor_sync(0xFFFFFFFFu, mval, 1);
            mval += __shfl_xor_sync(0xFFFFFFFFu, mval, 2);
            const float m = mval * 0.015625f;
            float v = 0.f;
            #pragma unroll
            for (int i = 0; i < 16; i++) { float d = X1[(g + 4 * i) * 68 + f] - m; v = fmaf(d, d, v); }
            v += __shfl_xor_sync(0xFFFFFFFFu, v, 1);
            v += __shfl_xor_sync(0xFFFFFFFFu, v, 2);
            const float inv = rsqrtf(fmaf(v, 0.015625f, 1e-5f));
            #pragma unroll
            for (int i = 0; i < 16; i++) {
                const int idx = (g + 4 * i) * 68 + f;
                X1[idx] = (X1[idx] - m) * inv;
            }
        }
        __syncthreads();

        // --- hp1 = x1 @ w1, fused s1/d1 ---
        {
            const int p  = tid >> 2;
            const int j4 = tid & 3;
            const int ob = j4 << 3;
            u64 acc[4] = {0, 0, 0, 0};
            #pragma unroll
            for (int f = 0; f < 64; f++) {
                float xv = X1[p * 68 + f];
                u64 xx = pk2(xv, xv);
                const ulonglong2* w = reinterpret_cast<const ulonglong2*>(W1S + f * 32 + ob);
                #pragma unroll
                for (int j = 0; j < 2; j++) {
                    ulonglong2 ww = w[j];
                    acc[2*j]   = ffma2(ww.x, xx, acc[2*j]);
                    acc[2*j+1] = ffma2(ww.y, xx, acc[2*j+1]);
                }
            }
            float sv = 0.f, dv = 0.f;
            #pragma unroll
            for (int j = 0; j < 4; j++) {
                float v0 = lo2(acc[j]), v1 = hi2(acc[j]);
                sv = fmaf(v0, A1S[ob + 2*j], sv); sv = fmaf(v1, A1S[ob + 2*j + 1], sv);
                dv = fmaf(v0, A1D[ob + 2*j], dv); dv = fmaf(v1, A1D[ob + 2*j + 1], dv);
            }
            sv += __shfl_xor_sync(0xFFFFFFFFu, sv, 1);
            sv += __shfl_xor_sync(0xFFFFFFFFu, sv, 2);
            dv += __shfl_xor_sync(0xFFFFFFFFu, dv, 1);
            dv += __shfl_xor_sync(0xFFFFFFFFu, dv, 2);
            if (j4 == 0) { S1[p] = sv; D1[p] = dv; }
            u64* dst = reinterpret_cast<u64*>(HP1 + p * 36 + ob);
            #pragma unroll
            for (int j = 0; j < 4; j++) dst[j] = acc[j];
        }
        __syncthreads();

        // --- softmax1 weights (EM overlays dead HP0) ---
        {
            const int p = tid >> 2, qh = tid & 3;
            const float sp = S1[p];
            const float* dq = D1 + qh * 16;
            float den = 0.f;
            #pragma unroll
            for (int v4 = 0; v4 < 4; v4++) {
                float4 dv4 = *(const float4*)(dq + v4 * 4);
                float e[4] = {dv4.x, dv4.y, dv4.z, dv4.w};
                float w[4];
                #pragma unroll
                for (int i = 0; i < 4; i++) {
                    float ev = sp + e[i];
                    ev = ev > 0.f ? ev : 0.2f * ev;
                    w[i] = __expf(ev);
                    den += w[i];
                }
                *(float4*)(EM + p * 68 + qh * 16 + v4 * 4) = make_float4(w[0], w[1], w[2], w[3]);
            }
            den += __shfl_xor_sync(0xFFFFFFFFu, den, 1);
            den += __shfl_xor_sync(0xFFFFFFFFu, den, 2);
            if (qh == 0) ES[p] = __fdividef(1.f, den);
        }
        __syncthreads();

        // --- apply attn1, write graph_in ---
        {
            const int p  = tid >> 2;
            const int ob = (tid & 3) << 3;
            u64 acc[4] = {0, 0, 0, 0};
            const float* ew = EM + p * 68;
            #pragma unroll 2
            for (int qb = 0; qb < 16; qb++) {
                float4 w4 = *(const float4*)(ew + qb * 4);
                float wv[4] = {w4.x, w4.y, w4.z, w4.w};
                #pragma unroll
                for (int i = 0; i < 4; i++) {
                    u64 ww = pk2(wv[i], wv[i]);
                    const ulonglong2* hq = reinterpret_cast<const ulonglong2*>(
                        HP1 + (qb * 4 + i) * 36 + ob);
                    ulonglong2 h0q = hq[0], h1q = hq[1];
                    acc[0] = ffma2(h0q.x, ww, acc[0]); acc[1] = ffma2(h0q.y, ww, acc[1]);
                    acc[2] = ffma2(h1q.x, ww, acc[2]); acc[3] = ffma2(h1q.y, ww, acc[3]);
                }
            }
            float inv = ES[p];
            float2* gp = reinterpret_cast<float2*>(
                gout + ((size_t)t * NTOT + s * 64 + p) * 32 + ob);
            #pragma unroll
            for (int j = 0; j < 4; j++) {
                float v0 = fmaf(lo2(acc[j]), inv, B1[ob + 2 * j]);
                float v1 = fmaf(hi2(acc[j]), inv, B1[ob + 2 * j + 1]);
                gp[j] = make_float2(v0, v1);
            }
        }
    }
}

// ---------------------------------------------------------------------------
#define LSTM3_SMEM_BYTES  ((128*34 + 128*5 + 2*32*34 + 8*3*34) * 8)
#define LSTM32_SMEM_BYTES ((128*34 + 2*32*34) * 8)

extern "C" void kernel_launch(void* const* d_in, const int* in_sizes, int n_in,
                              void* d_out, int out_size)
{
    (void)in_sizes; (void)n_in; (void)out_size;
    const float* obs  = (const float*)d_in[0];
    const float* h0t  = (const float*)d_in[1];
    const float* c0t  = (const float*)d_in[2];
    const float* h0g  = (const float*)d_in[3];
    const float* c0g  = (const float*)d_in[4];
    const float* zn   = (const float*)d_in[5];
    const float* WihT = (const float*)d_in[6];
    const float* WhhT = (const float*)d_in[7];
    const float* bihT = (const float*)d_in[8];
    const float* bhhT = (const float*)d_in[9];
    const float* WihG = (const float*)d_in[10];
    const float* WhhG = (const float*)d_in[11];
    const float* bihG = (const float*)d_in[12];
    const float* bhhG = (const float*)d_in[13];
    const float* w0   = (const float*)d_in[14];
    const float* as0  = (const float*)d_in[15];
    const float* ad0  = (const float*)d_in[16];
    const float* b0   = (const float*)d_in[17];
    const float* w1   = (const float*)d_in[18];
    const float* as1  = (const float*)d_in[19];
    const float* ad1  = (const float*)d_in[20];
    const float* b1   = (const float*)d_in[21];

    float* out = (float*)d_out;
    float* enc = out;                                  // [N,72]
    float* ghs = out + (size_t)NTOT * 72;              // [T,N,32]
    float* ths = ghs + (size_t)TT * NTOT * 32;         // [T,N,32]

    float* gin = nullptr;
    cudaGetSymbolAddress((void**)&gin, g_graph_in);
    u64* xgp = nullptr;
    cudaGetSymbolAddress((void**)&xgp, g_xg);

    cudaFuncSetAttribute(lstm_kernel<3, false, false>,
                         cudaFuncAttributeMaxDynamicSharedMemorySize, LSTM3_SMEM_BYTES);
    cudaFuncSetAttribute(lstm_kernel<32, true, true>,
                         cudaFuncAttributeMaxDynamicSharedMemorySize, LSTM32_SMEM_BYTES);
    cudaFuncSetAttribute(gat_kernel,
                         cudaFuncAttributeMaxDynamicSharedMemorySize, GAT_SMEM_BYTES);

    // 1) traj LSTM -> traj_hs
    lstm_kernel<3, false, false><<<NTOT / 64, 256, LSTM3_SMEM_BYTES>>>(
        obs, h0t, c0t, WihT, WhhT, bihT, bhhT, ths, nullptr, nullptr, nullptr, nullptr);

    // 2) GAT encoder -> graph_in (2 tiles per block)
    gat_kernel<<<NS * TT / 2, 256, GAT_SMEM_BYTES>>>(
        ths, w0, as0, ad0, b0, w1, as1, ad1, b1, gin);

    // 3) precompute input-gate contributions for graph LSTM
    xg_kernel<<<TT * 512, 256>>>(gin, WihG, bihG, bhhG, xgp);

    // 4) graph LSTM (h-GEMM only) -> graph_hs + encoded
    lstm_kernel<32, true, true><<<NTOT / 64, 256, LSTM32_SMEM_BYTES>>>(
        nullptr, h0g, c0g, nullptr, WhhG, nullptr, nullptr, ghs, xgp,
        ths + (size_t)(TT - 1) * NTOT * 32, zn, enc);
}

// round 16
// speedup vs baseline: 1.0063x; 1.0063x over previous
#include <cuda_runtime.h>

#define TT   8
#define NS   512
#define NTOT 32768   // NS*NP

// Scratch: GAT output -> graph LSTM input ([T, N, 32])
__device__ float g_graph_in[(size_t)TT * NTOT * 32];
// Scratch: precomputed input-gate contributions for graph LSTM
__device__ unsigned long long g_xg[(size_t)TT * 16384 * 128];

typedef unsigned long long u64;
typedef unsigned int u32;

__device__ __forceinline__ u64 ffma2(u64 a, u64 b, u64 c) {
    u64 d;
    asm("fma.rn.f32x2 %0, %1, %2, %3;" : "=l"(d) : "l"(a), "l"(b), "l"(c));
    return d;
}
__device__ __forceinline__ u64 pk2(float lo, float hi) {
    u64 r;
    asm("mov.b64 %0, {%1, %2};" : "=l"(r) : "f"(lo), "f"(hi));
    return r;
}
__device__ __forceinline__ float lo2(u64 v) { return __uint_as_float((unsigned)v); }
__device__ __forceinline__ float hi2(u64 v) { return __uint_as_float((unsigned)(v >> 32)); }

__device__ __forceinline__ float sigmf_(float x) {
    return __fdividef(1.f, 1.f + __expf(-x));
}
__device__ __forceinline__ float tanhf_(float x) {
    float e = __expf(-2.f * fabsf(x));
    float r = __fdividef(1.f - e, 1.f + e);
    return copysignf(r, x);
}

// ---------------------------------------------------------------------------
// xg_kernel: XG[t][pair][gate,k] = Wih @ x + (bih+bhh)  (unchanged from R14)
// ---------------------------------------------------------------------------
__global__ void __launch_bounds__(256, 2) xg_kernel(
    const float* __restrict__ gin,   // [T, N, 32]
    const float* __restrict__ Wih,   // [128, 32]
    const float* __restrict__ bih, const float* __restrict__ bhh,
    u64* __restrict__ xgp)
{
    __shared__ __align__(16) u64 WD[128 * 34];
    __shared__ __align__(16) u64 XP[32 * 34];
    __shared__ float SB[128];

    const int tid = threadIdx.x;
    const int b = blockIdx.x;
    const int t = b >> 9;
    const int pb = (b & 511) * 32;

    for (int i = tid; i < 128 * 32; i += 256) {
        int r = i >> 5, f = i & 31;
        float w = Wih[r * 32 + f];
        WD[r * 34 + f] = pk2(w, w);
    }
    if (tid < 128) SB[tid] = bih[tid] + bhh[tid];
    {
        const int p  = tid >> 2;
        const int fo = (tid & 3) << 3;
        const float4* xp = reinterpret_cast<const float4*>(
            gin + ((size_t)t * NTOT + 2 * pb + p) * 32 + fo);
        float4 A = xp[0], Bq = xp[1];
        float av[8] = {A.x, A.y, A.z, A.w, Bq.x, Bq.y, Bq.z, Bq.w};
        u32* XH = reinterpret_cast<u32*>(XP);
        #pragma unroll
        for (int e = 0; e < 8; e++)
            XH[2 * ((fo + e) * 34 + (p >> 1)) + (p & 1)] = __float_as_uint(av[e]);
    }
    __syncthreads();

    const int k   = tid & 31;
    const int pg4 = (tid >> 5) * 4;
    const int kb0 = (0 * 32 + k) * 34;
    const int kb1 = (1 * 32 + k) * 34;
    const int kb2 = (2 * 32 + k) * 34;
    const int kb3 = (3 * 32 + k) * 34;

    u64 aI[4] = {0,0,0,0}, aF[4] = {0,0,0,0}, aG[4] = {0,0,0,0}, aO[4] = {0,0,0,0};
    #pragma unroll
    for (int fo = 0; fo < 8; fo++) {
        const int f4 = fo * 4;
        u64 wv[4][4];
        {
            ulonglong2 q;
            q = *(const ulonglong2*)&WD[kb0 + f4];     wv[0][0] = q.x; wv[0][1] = q.y;
            q = *(const ulonglong2*)&WD[kb0 + f4 + 2]; wv[0][2] = q.x; wv[0][3] = q.y;
            q = *(const ulonglong2*)&WD[kb1 + f4];     wv[1][0] = q.x; wv[1][1] = q.y;
            q = *(const ulonglong2*)&WD[kb1 + f4 + 2]; wv[1][2] = q.x; wv[1][3] = q.y;
            q = *(const ulonglong2*)&WD[kb2 + f4];     wv[2][0] = q.x; wv[2][1] = q.y;
            q = *(const ulonglong2*)&WD[kb2 + f4 + 2]; wv[2][2] = q.x; wv[2][3] = q.y;
            q = *(const ulonglong2*)&WD[kb3 + f4];     wv[3][0] = q.x; wv[3][1] = q.y;
            q = *(const ulonglong2*)&WD[kb3 + f4 + 2]; wv[3][2] = q.x; wv[3][3] = q.y;
        }
        u64 xv[4][4];
        #pragma unroll
        for (int fp = 0; fp < 4; fp++) {
            ulonglong2 q0 = *(const ulonglong2*)&XP[(f4 + fp) * 34 + pg4];
            ulonglong2 q1 = *(const ulonglong2*)&XP[(f4 + fp) * 34 + pg4 + 2];
            xv[fp][0] = q0.x; xv[fp][1] = q0.y; xv[fp][2] = q1.x; xv[fp][3] = q1.y;
        }
        #pragma unroll
        for (int fp = 0; fp < 4; fp++) {
            #pragma unroll
            for (int pp = 0; pp < 4; pp++) {
                aI[pp] = ffma2(wv[0][fp], xv[fp][pp], aI[pp]);
                aF[pp] = ffma2(wv[1][fp], xv[fp][pp], aF[pp]);
                aG[pp] = ffma2(wv[2][fp], xv[fp][pp], aG[pp]);
                aO[pp] = ffma2(wv[3][fp], xv[fp][pp], aO[pp]);
            }
        }
    }

    const float bI = SB[k], bF = SB[32 + k], bG = SB[64 + k], bO = SB[96 + k];
    #pragma unroll
    for (int pp = 0; pp < 4; pp++) {
        u64* row = xgp + (((size_t)t * 16384 + pb + pg4 + pp) << 7);
        row[k]      = pk2(lo2(aI[pp]) + bI, hi2(aI[pp]) + bI);
        row[32 + k] = pk2(lo2(aF[pp]) + bF, hi2(aF[pp]) + bF);
        row[64 + k] = pk2(lo2(aG[pp]) + bG, hi2(aG[pp]) + bG);
        row[96 + k] = pk2(lo2(aO[pp]) + bO, hi2(aO[pp]) + bO);
    }
}

// ---------------------------------------------------------------------------
// LSTM as per-step tiled GEMM (unchanged from R14).
// ---------------------------------------------------------------------------
template<int D, bool ENC, bool XGM>
__global__ void __launch_bounds__(256, 2) lstm_kernel(
    const float* __restrict__ xseq,
    const float* __restrict__ h0, const float* __restrict__ c0,
    const float* __restrict__ Wih,
    const float* __restrict__ Whh,
    const float* __restrict__ bih, const float* __restrict__ bhh,
    float* __restrict__ hsout,
    const u64* __restrict__ xgp,
    const float* __restrict__ traj_last,
    const float* __restrict__ znoise,
    float* __restrict__ enc)
{
    constexpr int SWH    = 34;
    constexpr int SWX    = (D == 3) ? 5 : 34;
    constexpr int WDH_SZ = 128 * SWH;
    constexpr int WDX_SZ = XGM ? 0 : 128 * SWX;
    constexpr int HB_SZ  = 2 * 32 * 34;
    constexpr int HSTRIDE = 32 * 34;

    extern __shared__ __align__(16) u64 smU[];
    u64* WDH = smU;
    u64* WDX = WDH + WDH_SZ;
    u64* HB  = WDX + WDX_SZ;
    u64* XB  = HB + HB_SZ;

    const int tid  = threadIdx.x;
    const int k    = tid & 31;
    const int pg   = tid >> 5;
    const int pg4  = pg * 4;
    const int base = blockIdx.x * 64;

    for (int i = tid; i < 128 * 32; i += 256) {
        int r = i >> 5, f = i & 31;
        float w = Whh[r * 32 + f];
        WDH[r * SWH + f] = pk2(w, w);
    }
    if constexpr (!XGM) {
        if constexpr (D == 3) {
            for (int i = tid; i < 128 * 3; i += 256) {
                int r = i / 3, f = i - r * 3;
                float w = Wih[r * 3 + f];
                WDX[r * SWX + f] = pk2(w, w);
            }
        } else {
            for (int i = tid; i < 128 * 32; i += 256) {
                int r = i >> 5, f = i & 31;
                float w = Wih[r * 32 + f];
                WDX[r * SWX + f] = pk2(w, w);
            }
        }
    }

    float bI = 0.f, bF = 0.f, bG = 0.f, bO = 0.f;
    if constexpr (!XGM) {
        bI = bih[k]      + bhh[k];
        bF = bih[32 + k] + bhh[32 + k];
        bG = bih[64 + k] + bhh[64 + k];
        bO = bih[96 + k] + bhh[96 + k];
    }

    float c[8];
    {
        float hv0[8];
        #pragma unroll
        for (int j = 0; j < 8; j++) {
            c[j]   = c0[(size_t)(base + pg * 8 + j) * 32 + k];
            hv0[j] = h0[(size_t)(base + pg * 8 + j) * 32 + k];
        }
        u64* HN = HB + (size_t)k * 34 + pg4;
        #pragma unroll
        for (int jj = 0; jj < 4; jj++) HN[jj] = pk2(hv0[2*jj], hv0[2*jj+1]);
    }

    if constexpr (!XGM) {
        if constexpr (D == 3) {
            u32* XH = reinterpret_cast<u32*>(XB);
            for (int i = tid; i < 8 * 64 * 3; i += 256) {
                int tt  = i / 192;
                int rem = i - tt * 192;
                int p   = rem / 3;
                int xf  = rem - p * 3;
                float xv = xseq[((size_t)tt * NTOT + base + p) * 3 + xf];
                XH[2 * ((tt * 3 + xf) * 34 + (p >> 1)) + (p & 1)] = __float_as_uint(xv);
            }
        }
    }
    __syncthreads();

    const int kb0 = (0 * 32 + k) * SWH;
    const int kb1 = (1 * 32 + k) * SWH;
    const int kb2 = (2 * 32 + k) * SWH;
    const int kb3 = (3 * 32 + k) * SWH;

    #pragma unroll 1
    for (int t = 0; t < TT; t++) {
        u64 aI[4] = {0,0,0,0}, aF[4] = {0,0,0,0}, aG[4] = {0,0,0,0}, aO[4] = {0,0,0,0};
        u64 xI[4], xF[4], xGt[4], xO[4];

        const u64* HT = HB + (t & 1) * HSTRIDE;
        #pragma unroll
        for (int fo = 0; fo < 4; fo++) {
            const int f4 = fo * 4;
            u64 wv[4][4];
            {
                ulonglong2 q;
                q = *(const ulonglong2*)&WDH[kb0 + f4];     wv[0][0] = q.x; wv[0][1] = q.y;
                q = *(const ulonglong2*)&WDH[kb0 + f4 + 2]; wv[0][2] = q.x; wv[0][3] = q.y;
                q = *(const ulonglong2*)&WDH[kb1 + f4];     wv[1][0] = q.x; wv[1][1] = q.y;
                q = *(const ulonglong2*)&WDH[kb1 + f4 + 2]; wv[1][2] = q.x; wv[1][3] = q.y;
                q = *(const ulonglong2*)&WDH[kb2 + f4];     wv[2][0] = q.x; wv[2][1] = q.y;
                q = *(const ulonglong2*)&WDH[kb2 + f4 + 2]; wv[2][2] = q.x; wv[2][3] = q.y;
                q = *(const ulonglong2*)&WDH[kb3 + f4];     wv[3][0] = q.x; wv[3][1] = q.y;
                q = *(const ulonglong2*)&WDH[kb3 + f4 + 2]; wv[3][2] = q.x; wv[3][3] = q.y;
            }
            u64 hv[4][4];
            #pragma unroll
            for (int fp = 0; fp < 4; fp++) {
                ulonglong2 q0 = *(const ulonglong2*)&HT[(f4 + fp) * 34 + pg4];
                ulonglong2 q1 = *(const ulonglong2*)&HT[(f4 + fp) * 34 + pg4 + 2];
                hv[fp][0] = q0.x; hv[fp][1] = q0.y; hv[fp][2] = q1.x; hv[fp][3] = q1.y;
            }
            #pragma unroll
            for (int fp = 0; fp < 4; fp++) {
                #pragma unroll
                for (int pp = 0; pp < 4; pp++) {
                    aI[pp] = ffma2(wv[0][fp], hv[fp][pp], aI[pp]);
                    aF[pp] = ffma2(wv[1][fp], hv[fp][pp], aF[pp]);
                    aG[pp] = ffma2(wv[2][fp], hv[fp][pp], aG[pp]);
                    aO[pp] = ffma2(wv[3][fp], hv[fp][pp], aO[pp]);
                }
            }
        }

        if constexpr (XGM) {
            const u64* xr = xgp + ((size_t)t * 16384 + (base >> 1) + pg4) * 128;
            #pragma unroll
            for (int pp = 0; pp < 4; pp++) {
                const u64* r = xr + (size_t)pp * 128;
                xI[pp] = r[k]; xF[pp] = r[32 + k]; xGt[pp] = r[64 + k]; xO[pp] = r[96 + k];
            }
        }

        #pragma unroll
        for (int fo = 4; fo < 8; fo++) {
            const int f4 = fo * 4;
            u64 wv[4][4];
            {
                ulonglong2 q;
                q = *(const ulonglong2*)&WDH[kb0 + f4];     wv[0][0] = q.x; wv[0][1] = q.y;
                q = *(const ulonglong2*)&WDH[kb0 + f4 + 2]; wv[0][2] = q.x; wv[0][3] = q.y;
                q = *(const ulonglong2*)&WDH[kb1 + f4];     wv[1][0] = q.x; wv[1][1] = q.y;
                q = *(const ulonglong2*)&WDH[kb1 + f4 + 2]; wv[1][2] = q.x; wv[1][3] = q.y;
                q = *(const ulonglong2*)&WDH[kb2 + f4];     wv[2][0] = q.x; wv[2][1] = q.y;
                q = *(const ulonglong2*)&WDH[kb2 + f4 + 2]; wv[2][2] = q.x; wv[2][3] = q.y;
                q = *(const ulonglong2*)&WDH[kb3 + f4];     wv[3][0] = q.x; wv[3][1] = q.y;
                q = *(const ulonglong2*)&WDH[kb3 + f4 + 2]; wv[3][2] = q.x; wv[3][3] = q.y;
            }
            u64 hv[4][4];
            #pragma unroll
            for (int fp = 0; fp < 4; fp++) {
                ulonglong2 q0 = *(const ulonglong2*)&HT[(f4 + fp) * 34 + pg4];
                ulonglong2 q1 = *(const ulonglong2*)&HT[(f4 + fp) * 34 + pg4 + 2];
                hv[fp][0] = q0.x; hv[fp][1] = q0.y; hv[fp][2] = q1.x; hv[fp][3] = q1.y;
            }
            #pragma unroll
            for (int fp = 0; fp < 4; fp++) {
                #pragma unroll
                for (int pp = 0; pp < 4; pp++) {
                    aI[pp] = ffma2(wv[0][fp], hv[fp][pp], aI[pp]);
                    aF[pp] = ffma2(wv[1][fp], hv[fp][pp], aF[pp]);
                    aG[pp] = ffma2(wv[2][fp], hv[fp][pp], aG[pp]);
                    aO[pp] = ffma2(wv[3][fp], hv[fp][pp], aO[pp]);
                }
            }
        }

        if constexpr (!XGM && D == 3) {
            const u64* XT = XB + (size_t)t * (3 * 34);
            const int xb0 = (0 * 32 + k) * SWX;
            const int xb1 = (1 * 32 + k) * SWX;
            const int xb2 = (2 * 32 + k) * SWX;
            const int xb3 = (3 * 32 + k) * SWX;
            #pragma unroll
            for (int xf = 0; xf < 3; xf++) {
                u64 wI = WDX[xb0 + xf], wF = WDX[xb1 + xf];
                u64 wG = WDX[xb2 + xf], wO = WDX[xb3 + xf];
                ulonglong2 q0 = *(const ulonglong2*)&XT[xf * 34 + pg4];
                ulonglong2 q1 = *(const ulonglong2*)&XT[xf * 34 + pg4 + 2];
                u64 xv[4] = {q0.x, q0.y, q1.x, q1.y};
                #pragma unroll
                for (int pp = 0; pp < 4; pp++) {
                    aI[pp] = ffma2(wI, xv[pp], aI[pp]);
                    aF[pp] = ffma2(wF, xv[pp], aF[pp]);
                    aG[pp] = ffma2(wG, xv[pp], aG[pp]);
                    aO[pp] = ffma2(wO, xv[pp], aO[pp]);
                }
            }
        }

        float hvec[8];
        #pragma unroll
        for (int pp = 0; pp < 4; pp++) {
            {
                const int p = 2 * pp;
                float gi = lo2(aI[pp]) + (XGM ? lo2(xI[pp])  : bI);
                float gf = lo2(aF[pp]) + (XGM ? lo2(xF[pp])  : bF);
                float gg = lo2(aG[pp]) + (XGM ? lo2(xGt[pp]) : bG);
                float go = lo2(aO[pp]) + (XGM ? lo2(xO[pp])  : bO);
                float cn = sigmf_(gf) * c[p] + sigmf_(gi) * tanhf_(gg);
                c[p] = cn;
                hvec[p] = sigmf_(go) * tanhf_(cn);
            }
            {
                const int p = 2 * pp + 1;
                float gi = hi2(aI[pp]) + (XGM ? hi2(xI[pp])  : bI);
                float gf = hi2(aF[pp]) + (XGM ? hi2(xF[pp])  : bF);
                float gg = hi2(aG[pp]) + (XGM ? hi2(xGt[pp]) : bG);
                float go = hi2(aO[pp]) + (XGM ? hi2(xO[pp])  : bO);
                float cn = sigmf_(gf) * c[p] + sigmf_(gi) * tanhf_(gg);
                c[p] = cn;
                hvec[p] = sigmf_(go) * tanhf_(cn);
            }
        }

        const int pedbase = base + pg * 8;
        #pragma unroll
        for (int j = 0; j < 8; j++)
            hsout[((size_t)t * NTOT + pedbase + j) * 32 + k] = hvec[j];

        if (t < TT - 1) {
            u64* HN = HB + ((t + 1) & 1) * HSTRIDE + (size_t)k * 34 + pg4;
            #pragma unroll
            for (int jj = 0; jj < 4; jj++) HN[jj] = pk2(hvec[2*jj], hvec[2*jj+1]);
            __syncthreads();
        } else if (ENC) {
            #pragma unroll
            for (int j = 0; j < 8; j++) {
                float* ep = enc + (size_t)(pedbase + j) * 72;
                ep[32 + k] = hvec[j];
                ep[k] = traj_last[(size_t)(pedbase + j) * 32 + k];
            }
            if (k < 8) {
                const float z = znoise[(size_t)blockIdx.x * 8 + k];
                #pragma unroll
                for (int j = 0; j < 8; j++)
                    enc[(size_t)(pedbase + j) * 72 + 64 + k] = z;
            }
        }
    }
}

// ---------------------------------------------------------------------------
// GAT encoder v3: 1 tile/block, attn0 with chunk-16 batched exp (MUFU
// pipelined), ELU via __expf, fused s/d epilogues, EM overlays dead HP0.
// ---------------------------------------------------------------------------
#define GAT_SMEM_FLOATS 18160
#define GAT_SMEM_BYTES  (GAT_SMEM_FLOATS * 4)

__global__ void __launch_bounds__(256, 3) gat_kernel(
    const float* __restrict__ trajhs,   // [T, N, 32]
    const float* __restrict__ w0,       // [4,32,16]
    const float* __restrict__ asrc0, const float* __restrict__ adst0,  // [4,16]
    const float* __restrict__ bias0,    // [16]
    const float* __restrict__ w1,       // [1,64,32]
    const float* __restrict__ asrc1, const float* __restrict__ adst1,  // [32]
    const float* __restrict__ bias1,    // [32]
    float* __restrict__ gout)           // [T, N, 32]
{
    extern __shared__ __align__(16) float sm[];
    float* XN  = sm;           // 64 x 33   (dead after hp0)
    float* W0S = sm + 2112;    // 32 x 64
    float* HP0 = sm + 4160;    // 64 x 68   (dead after attn0)
    float* EM  = sm + 4160;    // overlays HP0
    float* S0  = sm + 8512;    // 4 x 64
    float* D0  = sm + 8768;    // 4 x 64
    float* X1  = sm + 9024;    // 64 x 68
    float* W1S = sm + 13376;   // 64 x 32
    float* HP1 = sm + 15424;   // 64 x 36
    float* S1  = sm + 17728;   // 64
    float* D1  = sm + 17792;   // 64
    float* ES  = sm + 17856;   // 64
    float* A0S = sm + 17920;   // 64
    float* A0D = sm + 17984;   // 64
    float* A1S = sm + 18048;   // 32
    float* A1D = sm + 18080;   // 32
    float* B0  = sm + 18112;   // 16
    float* B1  = sm + 18128;   // 32

    const int tid = threadIdx.x;
    const int b = blockIdx.x;
    const int s = b >> 3, t = b & 7;

    const float* src = trajhs + ((size_t)t * NTOT + s * 64) * 32;
    for (int i = tid; i < 2048; i += 256) XN[(i >> 5) * 33 + (i & 31)] = src[i];
    for (int i = tid; i < 2048; i += 256) {
        int f = i >> 6, cc = i & 63;
        W0S[i] = w0[((cc >> 4) << 9) + (f << 4) + (cc & 15)];
    }
    for (int i = tid; i < 2048; i += 256) W1S[i] = w1[i];
    if (tid < 64)       { A0S[tid] = asrc0[tid]; A0D[tid] = adst0[tid]; }
    else if (tid < 96)  { A1S[tid - 64] = asrc1[tid - 64]; A1D[tid - 64] = adst1[tid - 64]; }
    else if (tid < 112) { B0[tid - 96] = bias0[tid - 96]; }
    else if (tid < 144) { B1[tid - 112] = bias1[tid - 112]; }
    __syncthreads();

    // --- instance norm 0 ---
    {
        const int f = tid >> 3, g = tid & 7;
        float mval = 0.f;
        #pragma unroll
        for (int i = 0; i < 8; i++) mval += XN[(g + 8 * i) * 33 + f];
        mval += __shfl_xor_sync(0xFFFFFFFFu, mval, 1);
        mval += __shfl_xor_sync(0xFFFFFFFFu, mval, 2);
        mval += __shfl_xor_sync(0xFFFFFFFFu, mval, 4);
        const float m = mval * 0.015625f;
        float v = 0.f;
        #pragma unroll
        for (int i = 0; i < 8; i++) { float d = XN[(g + 8 * i) * 33 + f] - m; v = fmaf(d, d, v); }
        v += __shfl_xor_sync(0xFFFFFFFFu, v, 1);
        v += __shfl_xor_sync(0xFFFFFFFFu, v, 2);
        v += __shfl_xor_sync(0xFFFFFFFFu, v, 4);
        const float inv = rsqrtf(fmaf(v, 0.015625f, 1e-5f));
        #pragma unroll
        for (int i = 0; i < 8; i++) {
            const int idx = (g + 8 * i) * 33 + f;
            XN[idx] = (XN[idx] - m) * inv;
        }
    }
    __syncthreads();

    // --- hp0 = xn @ w0, fused s0/d0 ---
    {
        const int p  = tid >> 2;
        const int h  = tid & 3;
        const int cb = h << 4;
        u64 acc[8] = {0, 0, 0, 0, 0, 0, 0, 0};
        #pragma unroll
        for (int f = 0; f < 32; f++) {
            float xv = XN[p * 33 + f];
            u64 xx = pk2(xv, xv);
            const ulonglong2* w = reinterpret_cast<const ulonglong2*>(W0S + f * 64 + cb);
            #pragma unroll
            for (int j = 0; j < 4; j++) {
                ulonglong2 ww = w[j];
                acc[2*j]   = ffma2(ww.x, xx, acc[2*j]);
                acc[2*j+1] = ffma2(ww.y, xx, acc[2*j+1]);
            }
        }
        float sv = 0.f, dv = 0.f;
        #pragma unroll
        for (int j = 0; j < 8; j++) {
            float v0 = lo2(acc[j]), v1 = hi2(acc[j]);
            sv = fmaf(v0, A0S[cb + 2*j], sv); sv = fmaf(v1, A0S[cb + 2*j + 1], sv);
            dv = fmaf(v0, A0D[cb + 2*j], dv); dv = fmaf(v1, A0D[cb + 2*j + 1], dv);
        }
        S0[h * 64 + p] = sv;
        D0[h * 64 + p] = dv;
        u64* dst = reinterpret_cast<u64*>(HP0 + p * 68 + cb);
        #pragma unroll
        for (int j = 0; j < 8; j++) dst[j] = acc[j];
    }
    __syncthreads();

    // --- attention0: chunk-16 batched exp, then pure FFMA2 block -> X1 ---
    {
        const int h = tid >> 6, p = tid & 63;
        const float sp = S0[h * 64 + p];
        const float* dd = D0 + h * 64;
        u64 acc[8] = {0, 0, 0, 0, 0, 0, 0, 0};
        float den0 = 0.f, den1 = 0.f, den2 = 0.f, den3 = 0.f;
        #pragma unroll 1
        for (int qc = 0; qc < 4; qc++) {
            float w[16];
            #pragma unroll
            for (int v = 0; v < 4; v++) {
                float4 d4 = *(const float4*)(dd + qc * 16 + v * 4);
                float e0 = sp + d4.x, e1 = sp + d4.y, e2 = sp + d4.z, e3 = sp + d4.w;
                e0 = e0 > 0.f ? e0 : 0.2f * e0;
                e1 = e1 > 0.f ? e1 : 0.2f * e1;
                e2 = e2 > 0.f ? e2 : 0.2f * e2;
                e3 = e3 > 0.f ? e3 : 0.2f * e3;
                w[v*4]   = __expf(e0); w[v*4+1] = __expf(e1);
                w[v*4+2] = __expf(e2); w[v*4+3] = __expf(e3);
            }
            #pragma unroll
            for (int v = 0; v < 4; v++) {
                den0 += w[v*4]; den1 += w[v*4+1]; den2 += w[v*4+2]; den3 += w[v*4+3];
            }
            #pragma unroll
            for (int i = 0; i < 16; i++) {
                u64 ww = pk2(w[i], w[i]);
                const ulonglong2* hq = reinterpret_cast<const ulonglong2*>(
                    HP0 + (qc * 16 + i) * 68 + h * 16);
                ulonglong2 h0q = hq[0], h1q = hq[1], h2q = hq[2], h3q = hq[3];
                acc[0] = ffma2(h0q.x, ww, acc[0]); acc[1] = ffma2(h0q.y, ww, acc[1]);
                acc[2] = ffma2(h1q.x, ww, acc[2]); acc[3] = ffma2(h1q.y, ww, acc[3]);
                acc[4] = ffma2(h2q.x, ww, acc[4]); acc[5] = ffma2(h2q.y, ww, acc[5]);
                acc[6] = ffma2(h3q.x, ww, acc[6]); acc[7] = ffma2(h3q.y, ww, acc[7]);
            }
        }
        float inv = __fdividef(1.f, (den0 + den1) + (den2 + den3));
        float* xo = X1 + p * 68 + h * 16;
        #pragma unroll
        for (int j = 0; j < 8; j++) {
            float v0 = fmaf(lo2(acc[j]), inv, B0[2 * j]);
            float v1 = fmaf(hi2(acc[j]), inv, B0[2 * j + 1]);
            v0 = v0 > 0.f ? v0 : (__expf(v0) - 1.f);
            v1 = v1 > 0.f ? v1 : (__expf(v1) - 1.f);
            xo[2 * j] = v0;
            xo[2 * j + 1] = v1;
        }
    }
    __syncthreads();

    // --- instance norm 1 ---
    {
        const int f = tid >> 2, g = tid & 3;
        float mval = 0.f;
        #pragma unroll
        for (int i = 0; i < 16; i++) mval += X1[(g + 4 * i) * 68 + f];
        mval += __shfl_xor_sync(0xFFFFFFFFu, mval, 1);
        mval += __shfl_xor_sync(0xFFFFFFFFu, mval, 2);
        const float m = mval * 0.015625f;
        float v = 0.f;
        #pragma unroll
        for (int i = 0; i < 16; i++) { float d = X1[(g + 4 * i) * 68 + f] - m; v = fmaf(d, d, v); }
        v += __shfl_xor_sync(0xFFFFFFFFu, v, 1);
        v += __shfl_xor_sync(0xFFFFFFFFu, v, 2);
        const float inv = rsqrtf(fmaf(v, 0.015625f, 1e-5f));
        #pragma unroll
        for (int i = 0; i < 16; i++) {
            const int idx = (g + 4 * i) * 68 + f;
            X1[idx] = (X1[idx] - m) * inv;
        }
    }
    __syncthreads();

    // --- hp1 = x1 @ w1, fused s1/d1 ---
    {
        const int p  = tid >> 2;
        const int j4 = tid & 3;
        const int ob = j4 << 3;
        u64 acc[4] = {0, 0, 0, 0};
        #pragma unroll
        for (int f = 0; f < 64; f++) {
            float xv = X1[p * 68 + f];
            u64 xx = pk2(xv, xv);
            const ulonglong2* w = reinterpret_cast<const ulonglong2*>(W1S + f * 32 + ob);
            #pragma unroll
            for (int j = 0; j < 2; j++) {
                ulonglong2 ww = w[j];
                acc[2*j]   = ffma2(ww.x, xx, acc[2*j]);
                acc[2*j+1] = ffma2(ww.y, xx, acc[2*j+1]);
            }
        }
        float sv = 0.f, dv = 0.f;
        #pragma unroll
        for (int j = 0; j < 4; j++) {
            float v0 = lo2(acc[j]), v1 = hi2(acc[j]);
            sv = fmaf(v0, A1S[ob + 2*j], sv); sv = fmaf(v1, A1S[ob + 2*j + 1], sv);
            dv = fmaf(v0, A1D[ob + 2*j], dv); dv = fmaf(v1, A1D[ob + 2*j + 1], dv);
        }
        sv += __shfl_xor_sync(0xFFFFFFFFu, sv, 1);
        sv += __shfl_xor_sync(0xFFFFFFFFu, sv, 2);
        dv += __shfl_xor_sync(0xFFFFFFFFu, dv, 1);
        dv += __shfl_xor_sync(0xFFFFFFFFu, dv, 2);
        if (j4 == 0) { S1[p] = sv; D1[p] = dv; }
        u64* dst = reinterpret_cast<u64*>(HP1 + p * 36 + ob);
        #pragma unroll
        for (int j = 0; j < 4; j++) dst[j] = acc[j];
    }
    __syncthreads();

    // --- softmax1 weights (EM overlays dead HP0) ---
    {
        const int p = tid >> 2, qh = tid & 3;
        const float sp = S1[p];
        const float* dq = D1 + qh * 16;
        float den = 0.f;
        #pragma unroll
        for (int v4 = 0; v4 < 4; v4++) {
            float4 dv4 = *(const float4*)(dq + v4 * 4);
            float e[4] = {dv4.x, dv4.y, dv4.z, dv4.w};
            float w[4];
            #pragma unroll
            for (int i = 0; i < 4; i++) {
                float ev = sp + e[i];
                ev = ev > 0.f ? ev : 0.2f * ev;
                w[i] = __expf(ev);
                den += w[i];
            }
            *(float4*)(EM + p * 68 + qh * 16 + v4 * 4) = make_float4(w[0], w[1], w[2], w[3]);
        }
        den += __shfl_xor_sync(0xFFFFFFFFu, den, 1);
        den += __shfl_xor_sync(0xFFFFFFFFu, den, 2);
        if (qh == 0) ES[p] = __fdividef(1.f, den);
    }
    __syncthreads();

    // --- apply attn1, write graph_in ---
    {
        const int p  = tid >> 2;
        const int ob = (tid & 3) << 3;
        u64 acc[4] = {0, 0, 0, 0};
        const float* ew = EM + p * 68;
        #pragma unroll 2
        for (int qb = 0; qb < 16; qb++) {
            float4 w4 = *(const float4*)(ew + qb * 4);
            float wv[4] = {w4.x, w4.y, w4.z, w4.w};
            #pragma unroll
            for (int i = 0; i < 4; i++) {
                u64 ww = pk2(wv[i], wv[i]);
                const ulonglong2* hq = reinterpret_cast<const ulonglong2*>(
                    HP1 + (qb * 4 + i) * 36 + ob);
                ulonglong2 h0q = hq[0], h1q = hq[1];
                acc[0] = ffma2(h0q.x, ww, acc[0]); acc[1] = ffma2(h0q.y, ww, acc[1]);
                acc[2] = ffma2(h1q.x, ww, acc[2]); acc[3] = ffma2(h1q.y, ww, acc[3]);
            }
        }
        float inv = ES[p];
        float2* gp = reinterpret_cast<float2*>(
            gout + ((size_t)t * NTOT + s * 64 + p) * 32 + ob);
        #pragma unroll
        for (int j = 0; j < 4; j++) {
            float v0 = fmaf(lo2(acc[j]), inv, B1[ob + 2 * j]);
            float v1 = fmaf(hi2(acc[j]), inv, B1[ob + 2 * j + 1]);
            gp[j] = make_float2(v0, v1);
        }
    }
}

// ---------------------------------------------------------------------------
#define LSTM3_SMEM_BYTES  ((128*34 + 128*5 + 2*32*34 + 8*3*34) * 8)
#define LSTM32_SMEM_BYTES ((128*34 + 2*32*34) * 8)

extern "C" void kernel_launch(void* const* d_in, const int* in_sizes, int n_in,
                              void* d_out, int out_size)
{
    (void)in_sizes; (void)n_in; (void)out_size;
    const float* obs  = (const float*)d_in[0];
    const float* h0t  = (const float*)d_in[1];
    const float* c0t  = (const float*)d_in[2];
    const float* h0g  = (const float*)d_in[3];
    const float* c0g  = (const float*)d_in[4];
    const float* zn   = (const float*)d_in[5];
    const float* WihT = (const float*)d_in[6];
    const float* WhhT = (const float*)d_in[7];
    const float* bihT = (const float*)d_in[8];
    const float* bhhT = (const float*)d_in[9];
    const float* WihG = (const float*)d_in[10];
    const float* WhhG = (const float*)d_in[11];
    const float* bihG = (const float*)d_in[12];
    const float* bhhG = (const float*)d_in[13];
    const float* w0   = (const float*)d_in[14];
    const float* as0  = (const float*)d_in[15];
    const float* ad0  = (const float*)d_in[16];
    const float* b0   = (const float*)d_in[17];
    const float* w1   = (const float*)d_in[18];
    const float* as1  = (const float*)d_in[19];
    const float* ad1  = (const float*)d_in[20];
    const float* b1   = (const float*)d_in[21];

    float* out = (float*)d_out;
    float* enc = out;                                  // [N,72]
    float* ghs = out + (size_t)NTOT * 72;              // [T,N,32]
    float* ths = ghs + (size_t)TT * NTOT * 32;         // [T,N,32]

    float* gin = nullptr;
    cudaGetSymbolAddress((void**)&gin, g_graph_in);
    u64* xgp = nullptr;
    cudaGetSymbolAddress((void**)&xgp, g_xg);

    cudaFuncSetAttribute(lstm_kernel<3, false, false>,
                         cudaFuncAttributeMaxDynamicSharedMemorySize, LSTM3_SMEM_BYTES);
    cudaFuncSetAttribute(lstm_kernel<32, true, true>,
                         cudaFuncAttributeMaxDynamicSharedMemorySize, LSTM32_SMEM_BYTES);
    cudaFuncSetAttribute(gat_kernel,
                         cudaFuncAttributeMaxDynamicSharedMemorySize, GAT_SMEM_BYTES);

    // 1) traj LSTM -> traj_hs
    lstm_kernel<3, false, false><<<NTOT / 64, 256, LSTM3_SMEM_BYTES>>>(
        obs, h0t, c0t, WihT, WhhT, bihT, bhhT, ths, nullptr, nullptr, nullptr, nullptr);

    // 2) GAT encoder -> graph_in (1 tile per block)
    gat_kernel<<<NS * TT, 256, GAT_SMEM_BYTES>>>(
        ths, w0, as0, ad0, b0, w1, as1, ad1, b1, gin);

    // 3) precompute input-gate contributions for graph LSTM
    xg_kernel<<<TT * 512, 256>>>(gin, WihG, bihG, bhhG, xgp);

    // 4) graph LSTM (h-GEMM only) -> graph_hs + encoded
    lstm_kernel<32, true, true><<<NTOT / 64, 256, LSTM32_SMEM_BYTES>>>(
        nullptr, h0g, c0g, nullptr, WhhG, nullptr, nullptr, ghs, xgp,
        ths + (size_t)(TT - 1) * NTOT * 32, zn, enc);
}